// round 8
// baseline (speedup 1.0000x reference)
#include <cuda_runtime.h>
#include <cstdint>

#define BB 128
#define TT 2048

__device__ float g_bufA[(size_t)BB * TT * 180];
__device__ float g_bufB[(size_t)BB * TT * 180];
__device__ float g_mask[(size_t)BB * TT];
__device__ float g_h34[BB * 60];
__device__ float g_z[BB * 30];
__device__ float g_Uc[60 * 180];
__device__ float g_Wc[150 * 180];
__device__ float g_bc[2 * 180];

__host__ __device__ constexpr int padDim(int v) {
    int h = (v + 3) / 4 * 4;
    if (((h / 4) & 1) == 0) h += 4;
    return h;
}

__device__ __forceinline__ uint32_t smem_u32(const void* p) {
    uint32_t a;
    asm("{ .reg .u64 t; cvta.to.shared.u64 t, %1; cvt.u32.u64 %0, t; }" : "=r"(a) : "l"(p));
    return a;
}
__device__ __forceinline__ uint32_t mapa_shared(uint32_t local, uint32_t rank) {
    uint32_t r;
    asm("mapa.shared::cluster.u32 %0, %1, %2;" : "=r"(r) : "r"(local), "r"(rank));
    return r;
}
__device__ __forceinline__ void st_cluster_f32(uint32_t addr, float v) {
    asm volatile("st.shared::cluster.b32 [%0], %1;" :: "r"(addr), "r"(__float_as_uint(v)));
}
__device__ __forceinline__ void cluster_sync_() {
    asm volatile("barrier.cluster.arrive.aligned;" ::: "memory");
    asm volatile("barrier.cluster.wait.aligned;" ::: "memory");
}
// packed f32x2 helpers
__device__ __forceinline__ void ffma2(unsigned long long& c, unsigned long long a,
                                      unsigned long long b) {
    asm("fma.rn.f32x2 %0, %1, %2, %3;" : "=l"(c) : "l"(a), "l"(b), "l"(c));
}
__device__ __forceinline__ unsigned long long addf2(unsigned long long a, unsigned long long b) {
    unsigned long long c;
    asm("add.rn.f32x2 %0, %1, %2;" : "=l"(c) : "l"(a), "l"(b));
    return c;
}
__device__ __forceinline__ unsigned long long packdup(float a) {
    unsigned long long d;
    asm("mov.b64 %0, {%1, %1};" : "=l"(d) : "f"(a));
    return d;
}
__device__ __forceinline__ void unpack2(unsigned long long v, float& lo, float& hi) {
    asm("mov.b64 {%0, %1}, %2;" : "=f"(lo), "=f"(hi) : "l"(v));
}

__device__ __forceinline__ float hsig(float v) { return fminf(fmaxf(0.2f * v + 0.5f, 0.f), 1.f); }
__device__ __forceinline__ float sigm(float v) { return 1.f / (1.f + expf(-v)); }

// ================= persistent GRU: zr-packed f32x2, x direct from gmem ==================
// 32 clusters x 8 CTAs; cluster = 4 batch rows; CTA rank owns hidden tile [j0, j0+JT).
// Warp = (4 b) x (4 jj); lanes split K-quads 32 ways. h in smem (double-buffered),
// x loaded per-lane straight from gmem each step. Butterfly -> in-register epilogue
// -> DSMEM broadcast. One cluster barrier per step; 2 CTAs/SM overlap.
template <int H, int I, int NTH, bool HSIG, bool TANHA, bool UM, bool WSEQ>
__global__ void __cluster_dims__(8, 1, 1) __launch_bounds__(NTH, 2)
gru_kernel(const float* __restrict__ in_seq, const float* __restrict__ U,
           const float* __restrict__ W, const float* __restrict__ bias,
           const float* __restrict__ mask, float* __restrict__ out_seq)
{
    constexpr int BT = 4, JJT = 4;
    constexpr int HP = padDim(H), IP = padDim(I), KP = HP + IP;
    constexpr int HQ = HP / 4, IPQ = IP / 4, Q = HQ + IPQ;
    constexpr int MH = (HQ + 31) >> 5;
    constexpr int NX = (IPQ + 31) >> 5;
    constexpr int JT = (H + 7) / 8;
    constexpr int JG = (JT + JJT - 1) / JJT;
    constexpr int JTp = JG * JJT;
    constexpr int H3 = 3 * H;
    static_assert(NTH == 32 * JG, "threads");

    extern __shared__ float smem[];
    float* sW   = smem;                    // per jj: [zr interleaved 2*KP | h KP]
    float* sv   = sW + JTp * 3 * KP;       // 2*BT*HP double-buffered h
    float* sbz  = sv + 2 * BT * HP;
    float* sbr  = sbz + JTp;
    float* sbrh = sbr + JTp;
    float* sbxh = sbrh + JTp;
    constexpr int SMTOT = JTp * 3 * KP + 2 * BT * HP + 4 * JTp;

    const int tid  = threadIdx.x;
    const int rank = blockIdx.x & 7;
    const int ci   = blockIdx.x >> 3;
    const int b0   = ci * BT;
    const int j0   = rank * JT;

    for (int e = tid; e < SMTOT; e += NTH) smem[e] = 0.f;
    __syncthreads();

    // weights: k < HP -> U row k, k >= HP -> W row (k-HP); zero-padded
    for (int e = tid; e < JT * KP; e += NTH) {
        int jj = e / KP, k = e - jj * KP;
        int j = j0 + jj;
        float vz = 0.f, vr = 0.f, vh = 0.f;
        if (j < H) {
            if (k < HP) {
                if (k < H) { vz = U[k*H3 + j]; vr = U[k*H3 + H + j]; vh = U[k*H3 + 2*H + j]; }
            } else {
                int i = k - HP;
                if (i < I) { vz = W[i*H3 + j]; vr = W[i*H3 + H + j]; vh = W[i*H3 + 2*H + j]; }
            }
        }
        float* row = sW + jj * 3 * KP;
        row[2*k] = vz; row[2*k + 1] = vr; row[2*KP + k] = vh;
    }
    if (tid < JT) {
        int j = j0 + tid;
        if (j < H) {
            sbz[tid]  = bias[j] + bias[H3 + j];
            sbr[tid]  = bias[H + j] + bias[H3 + H + j];
            sbxh[tid] = bias[2*H + j];
            sbrh[tid] = bias[H3 + 2*H + j];
        }
    }
    __syncthreads();

    const uint32_t svu = smem_u32(sv);
    uint32_t rb[8];
#pragma unroll
    for (int r = 0; r < 8; r++) rb[r] = mapa_shared(svu, (uint32_t)r);
    cluster_sync_();

    const int w = tid >> 5, lane = tid & 31;
    const int m0 = (HQ > lane) ? ((HQ - lane + 31) >> 5) : 0;  // first x iter index
    const int oitem = ((lane & 1) << 3) | ((lane & 2) << 1) | ((lane & 4) >> 1) | ((lane & 8) >> 3);
    const int ob = oitem >> 2, ojl = oitem & 3;
    const int ojj = w * JJT + ojl;
    const int oj  = j0 + ojj;
    const bool oval = (lane < 16) && (ojj < JT) && (oj < H);

    int p = 0;
    for (int t = 0; t < TT; t++) {
        const int nxt = 1 - p;

        // per-lane x loads straight from gmem (latency hidden by h-phase)
        float4 xp[NX][BT];
        bool xv[NX];
#pragma unroll
        for (int k = 0; k < NX; k++) {
            int g4 = lane + ((m0 + k) << 5);
            xv[k] = g4 < Q;
#pragma unroll
            for (int b = 0; b < BT; b++)
                xp[k][b] = xv[k] ? *reinterpret_cast<const float4*>(
                                       in_seq + ((size_t)(b0 + b) * TT + t) * IP + (g4 - HQ) * 4)
                                 : make_float4(0.f, 0.f, 0.f, 0.f);
        }
        float mkv = 1.f;
        if (UM && lane < 16) mkv = __ldg(mask + (size_t)(b0 + ob) * TT + t);

        unsigned long long zr[16];
        float rh[16], xh[16];
#pragma unroll
        for (int a = 0; a < 16; a++) { zr[a] = 0ull; rh[a] = 0.f; xh[a] = 0.f; }

        const float* vc = sv + p * BT * HP;

        // ---- h-range
#pragma unroll
        for (int m = 0; m < MH; m++) {
            int g4 = lane + (m << 5);
            if (g4 < HQ) {
                float4 vb[BT];
                unsigned long long vv[BT][4];
#pragma unroll
                for (int b = 0; b < BT; b++) {
                    vb[b] = *reinterpret_cast<const float4*>(vc + b * HP + g4 * 4);
                    vv[b][0] = packdup(vb[b].x); vv[b][1] = packdup(vb[b].y);
                    vv[b][2] = packdup(vb[b].z); vv[b][3] = packdup(vb[b].w);
                }
#pragma unroll
                for (int jl = 0; jl < JJT; ++jl) {
                    const float* wb = sW + (w * JJT + jl) * 3 * KP;
                    ulonglong2 zA = *reinterpret_cast<const ulonglong2*>(wb + 8 * g4);
                    ulonglong2 zB = *reinterpret_cast<const ulonglong2*>(wb + 8 * g4 + 4);
                    float4 wh = *reinterpret_cast<const float4*>(wb + 2 * KP + 4 * g4);
#pragma unroll
                    for (int b = 0; b < BT; b++) {
                        const int a = b * JJT + jl;
                        ffma2(zr[a], vv[b][0], zA.x); ffma2(zr[a], vv[b][1], zA.y);
                        ffma2(zr[a], vv[b][2], zB.x); ffma2(zr[a], vv[b][3], zB.y);
                        rh[a] = fmaf(vb[b].x, wh.x, rh[a]); rh[a] = fmaf(vb[b].y, wh.y, rh[a]);
                        rh[a] = fmaf(vb[b].z, wh.z, rh[a]); rh[a] = fmaf(vb[b].w, wh.w, rh[a]);
                    }
                }
            }
        }
        // ---- x-range
#pragma unroll
        for (int k = 0; k < NX; k++) {
            if (xv[k]) {
                int g4 = lane + ((m0 + k) << 5);
                unsigned long long vv[BT][4];
#pragma unroll
                for (int b = 0; b < BT; b++) {
                    vv[b][0] = packdup(xp[k][b].x); vv[b][1] = packdup(xp[k][b].y);
                    vv[b][2] = packdup(xp[k][b].z); vv[b][3] = packdup(xp[k][b].w);
                }
#pragma unroll
                for (int jl = 0; jl < JJT; ++jl) {
                    const float* wb = sW + (w * JJT + jl) * 3 * KP;
                    ulonglong2 zA = *reinterpret_cast<const ulonglong2*>(wb + 8 * g4);
                    ulonglong2 zB = *reinterpret_cast<const ulonglong2*>(wb + 8 * g4 + 4);
                    float4 wh = *reinterpret_cast<const float4*>(wb + 2 * KP + 4 * g4);
#pragma unroll
                    for (int b = 0; b < BT; b++) {
                        const int a = b * JJT + jl;
                        ffma2(zr[a], vv[b][0], zA.x); ffma2(zr[a], vv[b][1], zA.y);
                        ffma2(zr[a], vv[b][2], zB.x); ffma2(zr[a], vv[b][3], zB.y);
                        xh[a] = fmaf(xp[k][b].x, wh.x, xh[a]);
                        xh[a] = fmaf(xp[k][b].y, wh.y, xh[a]);
                        xh[a] = fmaf(xp[k][b].z, wh.z, xh[a]);
                        xh[a] = fmaf(xp[k][b].w, wh.w, xh[a]);
                    }
                }
            }
        }

        // ---- splitting butterfly: 16 items over lane bits 0..3
#pragma unroll
        for (int s = 0; s < 4; ++s) {
            const int n = 16 >> (s + 1);
            const bool hi = (lane >> s) & 1;
#pragma unroll
            for (int i = 0; i < n; ++i) {
                unsigned long long sz = hi ? zr[i] : zr[i + n];
                float sr = hi ? rh[i] : rh[i + n];
                float sx = hi ? xh[i] : xh[i + n];
                unsigned long long rz = __shfl_xor_sync(0xffffffffu, sz, 1 << s);
                float rr = __shfl_xor_sync(0xffffffffu, sr, 1 << s);
                float rx = __shfl_xor_sync(0xffffffffu, sx, 1 << s);
                zr[i] = addf2(hi ? zr[i + n] : zr[i], rz);
                rh[i] = (hi ? rh[i + n] : rh[i]) + rr;
                xh[i] = (hi ? xh[i + n] : xh[i]) + rx;
            }
        }
        zr[0] = addf2(zr[0], __shfl_xor_sync(0xffffffffu, zr[0], 16));
        rh[0] += __shfl_xor_sync(0xffffffffu, rh[0], 16);
        xh[0] += __shfl_xor_sync(0xffffffffu, xh[0], 16);

        // ---- in-register epilogue on owner lanes
        if (oval) {
            float az, ar;
            unpack2(zr[0], az, ar);
            az += sbz[ojj]; ar += sbr[ojj];
            float arh = rh[0] + sbrh[ojj];
            float axh = xh[0] + sbxh[ojj];
            float z = HSIG ? hsig(az) : sigm(az);
            float r = HSIG ? hsig(ar) : sigm(ar);
            float hh = axh + r * arh;
            if (TANHA) hh = tanhf(hh);
            float hprev = vc[ob * HP + oj];
            float hn = z * hprev + (1.f - z) * hh;
            if (UM) { if (mkv == 0.f) hn = hprev; }

            const uint32_t off = (uint32_t)(((nxt * BT + ob) * HP + oj) * 4);
#pragma unroll
            for (int r8 = 0; r8 < 8; r8++) st_cluster_f32(rb[r8] + off, hn);

            if (WSEQ) out_seq[((size_t)(b0 + ob) * TT + t) * HP + oj] = hn;
        }
        cluster_sync_();
        p = nxt;
    }

    if (!WSEQ) {
        if (tid < JT * BT) {
            const int b = tid & 3, jj = tid >> 2;
            const int j = j0 + jj;
            if (j < H) out_seq[(size_t)(b0 + b) * H + j] = sv[(p * BT + b) * HP + j];
        }
    }
}

// ===================== small kernels =====================
__global__ void mask_kernel(const float* __restrict__ x, float* __restrict__ m) {
    int idx = blockIdx.x * blockDim.x + threadIdx.x;
    if (idx < BB * TT) {
        float4 v = ((const float4*)x)[idx];
        m[idx] = (v.x != 0.f || v.y != 0.f || v.z != 0.f || v.w != 0.f) ? 1.f : 0.f;
    }
}

__global__ void combine34_kernel(const float* __restrict__ W3, const float* __restrict__ U3,
                                 const float* __restrict__ b3, const float* __restrict__ W4,
                                 const float* __restrict__ U4, const float* __restrict__ b4,
                                 float* __restrict__ Uc, float* __restrict__ Wc,
                                 float* __restrict__ bc) {
    const int NU = 60 * 180, NW = 150 * 180, NBc = 2 * 180;
    for (int e = blockIdx.x * blockDim.x + threadIdx.x; e < NU + NW + NBc;
         e += gridDim.x * blockDim.x) {
        if (e < NU) {
            int k = e / 180, col = e % 180;
            int g = col / 60, jj = col % 60;
            float v = 0.f;
            if (jj < 30) { if (k < 30)  v = U3[k * 90 + g * 30 + jj]; }
            else         { if (k >= 30) v = U4[(k - 30) * 90 + g * 30 + (jj - 30)]; }
            Uc[e] = v;
        } else if (e < NU + NW) {
            int e2 = e - NU;
            int i = e2 / 180, col = e2 % 180;
            int g = col / 60, jj = col % 60;
            Wc[e2] = (jj < 30) ? W3[i * 90 + g * 30 + jj] : W4[i * 90 + g * 30 + (jj - 30)];
        } else {
            int e2 = e - NU - NW;
            int rr = e2 / 180, col = e2 % 180;
            int g = col / 60, jj = col % 60;
            bc[e2] = (jj < 30) ? b3[rr * 90 + g * 30 + jj] : b4[rr * 90 + g * 30 + (jj - 30)];
        }
    }
}

__global__ void z_kernel(const float* __restrict__ h34, const float* __restrict__ eps,
                         float* __restrict__ z) {
    int idx = blockIdx.x * blockDim.x + threadIdx.x;
    if (idx < BB * 30) {
        int b = idx / 30, c = idx % 30;
        z[idx] = h34[b * 60 + c] + expf(0.5f * h34[b * 60 + 30 + c]) * eps[idx];
    }
}

__global__ void decin_kernel(const float* __restrict__ z, const float* __restrict__ tin2,
                             const float* __restrict__ masks, float* __restrict__ dec_in) {
    const size_t N = (size_t)BB * TT * 36;
    for (size_t idx = (size_t)blockIdx.x * blockDim.x + threadIdx.x; idx < N;
         idx += (size_t)gridDim.x * blockDim.x) {
        size_t b = idx / ((size_t)TT * 36);
        size_t rem = idx % ((size_t)TT * 36);
        size_t t = rem / 36;
        int c = (int)(rem % 36);
        float v = 0.f;
        if (c < 30)      v = z[b * 30 + c] * masks[(b * TT + t) * 32 + c];
        else if (c < 32) v = tin2[(b * TT + t) * 2 + (c - 30)] * masks[(b * TT + t) * 32 + c];
        dec_in[idx] = v;
    }
}

__global__ void dense_kernel(const float* __restrict__ h6, const float* __restrict__ Wd,
                             const float* __restrict__ bd, const float* __restrict__ dec_masks,
                             float* __restrict__ out) {
    int gtid = blockIdx.x * blockDim.x + threadIdx.x;
    int row = gtid >> 5;
    int lane = gtid & 31;
    if (row >= BB * TT) return;
    float s = 0.f;
    const float* hrow = h6 + (size_t)row * 180;
    for (int k = lane; k < 175; k += 32) s = fmaf(hrow[k], Wd[k], s);
#pragma unroll
    for (int off = 16; off; off >>= 1) s += __shfl_down_sync(0xffffffffu, s, off);
    if (lane == 0) out[row] = tanhf(s + bd[0]) * dec_masks[row];
}

// ===================== host-side launch helper =====================
template <int H, int I, int NTH, bool HSIG, bool TANHA, bool UM, bool WSEQ>
static void launch_gru(const float* in_seq, const float* U, const float* W, const float* bias,
                       const float* mask, float* out_seq) {
    constexpr int BT = 4, JJT = 4;
    constexpr int HP = padDim(H), IP = padDim(I), KP = HP + IP;
    constexpr int JT = (H + 7) / 8;
    constexpr int JG = (JT + JJT - 1) / JJT;
    constexpr int JTp = JG * JJT;
    constexpr int SMTOT = JTp * 3 * KP + 2 * BT * HP + 4 * JTp;
    constexpr int smem_bytes = SMTOT * 4;
    auto fn = gru_kernel<H, I, NTH, HSIG, TANHA, UM, WSEQ>;
    cudaFuncSetAttribute(fn, cudaFuncAttributeMaxDynamicSharedMemorySize, smem_bytes);
    cudaFuncSetAttribute(fn, cudaFuncAttributeNonPortableClusterSizeAllowed, 1);
    fn<<<256, NTH, smem_bytes>>>(in_seq, U, W, bias, mask, out_seq);
}

extern "C" void kernel_launch(void* const* d_in, const int* in_sizes, int n_in,
                              void* d_out, int out_size) {
    const float* x         = (const float*)d_in[0];
    const float* tin2      = (const float*)d_in[1];
    const float* masks     = (const float*)d_in[2];
    const float* dec_masks = (const float*)d_in[3];
    const float* eps       = (const float*)d_in[4];
    const float* W1 = (const float*)d_in[5];
    const float* U1 = (const float*)d_in[6];
    const float* b1 = (const float*)d_in[7];
    const float* W2 = (const float*)d_in[8];
    const float* U2 = (const float*)d_in[9];
    const float* b2 = (const float*)d_in[10];
    const float* W3 = (const float*)d_in[11];
    const float* U3 = (const float*)d_in[12];
    const float* b3 = (const float*)d_in[13];
    const float* W4 = (const float*)d_in[14];
    const float* U4 = (const float*)d_in[15];
    const float* b4 = (const float*)d_in[16];
    const float* W5 = (const float*)d_in[17];
    const float* U5 = (const float*)d_in[18];
    const float* b5 = (const float*)d_in[19];
    const float* W6 = (const float*)d_in[20];
    const float* U6 = (const float*)d_in[21];
    const float* b6 = (const float*)d_in[22];
    const float* Wd = (const float*)d_in[23];
    const float* bd = (const float*)d_in[24];
    float* out = (float*)d_out;

    void *pA, *pB, *pM, *pH34, *pZ, *pUc, *pWc, *pBc;
    cudaGetSymbolAddress(&pA, g_bufA);
    cudaGetSymbolAddress(&pB, g_bufB);
    cudaGetSymbolAddress(&pM, g_mask);
    cudaGetSymbolAddress(&pH34, g_h34);
    cudaGetSymbolAddress(&pZ, g_z);
    cudaGetSymbolAddress(&pUc, g_Uc);
    cudaGetSymbolAddress(&pWc, g_Wc);
    cudaGetSymbolAddress(&pBc, g_bc);
    float* bufA = (float*)pA;
    float* bufB = (float*)pB;
    float* mptr = (float*)pM;
    float* h34  = (float*)pH34;
    float* zbuf = (float*)pZ;
    float* Uc   = (float*)pUc;
    float* Wc   = (float*)pWc;
    float* Bc   = (float*)pBc;

    mask_kernel<<<(BB * TT + 255) / 256, 256>>>(x, mptr);
    combine34_kernel<<<64, 256>>>(W3, U3, b3, W4, U4, b4, Uc, Wc, Bc);

    // encoder GRU1 (H=175, I=4)
    launch_gru<175, 4, 192, true, true, true, true>(x, U1, W1, b1, mptr, bufA);
    // encoder GRU2 (H=150, I=175)
    launch_gru<150, 175, 160, true, true, true, true>(bufA, U2, W2, b2, mptr, bufB);
    // fused GRU3+GRU4 (H=60, I=150), final state only
    launch_gru<60, 150, 64, false, false, true, false>(bufB, Uc, Wc, Bc, mptr, h34);

    z_kernel<<<(BB * 30 + 255) / 256, 256>>>(h34, eps, zbuf);
    decin_kernel<<<2048, 256>>>(zbuf, tin2, masks, bufA);

    // decoder GRU5 (H=150, I=32)
    launch_gru<150, 32, 160, true, true, false, true>(bufA, U5, W5, b5, nullptr, bufB);
    // decoder GRU6 (H=175, I=150)
    launch_gru<175, 150, 192, true, true, false, true>(bufB, U6, W6, b6, nullptr, bufA);

    dense_kernel<<<(BB * TT + 7) / 8, 256>>>(bufA, Wd, bd, dec_masks, out);
}

// round 10
// speedup vs baseline: 1.1905x; 1.1905x over previous
#include <cuda_runtime.h>
#include <cstdint>

#define BB 128
#define TT 2048

__device__ float g_bufA[(size_t)BB * TT * 180];
__device__ float g_bufB[(size_t)BB * TT * 180];
__device__ float g_mask[(size_t)BB * TT];
__device__ float g_h34[BB * 60];
__device__ float g_z[BB * 30];
__device__ float g_Uc[60 * 180];
__device__ float g_Wc[150 * 180];
__device__ float g_bc[2 * 180];

__host__ __device__ constexpr int padDim(int v) {
    int h = (v + 3) / 4 * 4;
    if (((h / 4) & 1) == 0) h += 4;
    return h;
}

__device__ __forceinline__ uint32_t smem_u32(const void* p) {
    uint32_t a;
    asm("{ .reg .u64 t; cvta.to.shared.u64 t, %1; cvt.u32.u64 %0, t; }" : "=r"(a) : "l"(p));
    return a;
}
__device__ __forceinline__ uint32_t mapa_shared(uint32_t local, uint32_t rank) {
    uint32_t r;
    asm("mapa.shared::cluster.u32 %0, %1, %2;" : "=r"(r) : "r"(local), "r"(rank));
    return r;
}
__device__ __forceinline__ void st_cluster_f32(uint32_t addr, float v) {
    asm volatile("st.shared::cluster.b32 [%0], %1;" :: "r"(addr), "r"(__float_as_uint(v)));
}
__device__ __forceinline__ void cluster_sync_() {
    asm volatile("barrier.cluster.arrive.aligned;" ::: "memory");
    asm volatile("barrier.cluster.wait.aligned;" ::: "memory");
}
__device__ __forceinline__ void cp_async16(uint32_t dst, const void* src) {
    asm volatile("cp.async.cg.shared.global [%0], [%1], 16;" :: "r"(dst), "l"(src));
}
__device__ __forceinline__ void cp_async4(uint32_t dst, const void* src) {
    asm volatile("cp.async.ca.shared.global [%0], [%1], 4;" :: "r"(dst), "l"(src));
}
__device__ __forceinline__ void cp_commit() {
    asm volatile("cp.async.commit_group;" ::: "memory");
}
__device__ __forceinline__ void cp_wait0() {
    asm volatile("cp.async.wait_group 0;" ::: "memory");
}

__device__ __forceinline__ float hsig(float v) { return fminf(fmaxf(0.2f * v + 0.5f, 0.f), 1.f); }
__device__ __forceinline__ float sigm(float v) { return 1.f / (1.f + expf(-v)); }

// ============ persistent GRU: JJT=2 (balanced warps), register-tiled ============
// 32 clusters x 8 CTAs; cluster = BT=4 batch rows; CTA rank owns hidden tile
// [j0, j0+JT). One warp = (4 b) x (2 jj); lanes split K-quads 32 ways.
// 32 scalar f32 accumulators -> 3 splitting butterfly rounds + 2 broadcast
// rounds leave all 4 gate sums in the owner lane -> in-register epilogue ->
// DSMEM broadcast. cp.async double-buffered x staging. One cluster barrier
// per step; 2 CTAs/SM so one cluster's sync latency hides under the other.
template <int H, int I, int NTH, bool HSIG, bool TANHA, bool UM, bool WSEQ>
__global__ void __cluster_dims__(8, 1, 1) __launch_bounds__(NTH, 2)
gru_kernel(const float* __restrict__ in_seq, const float* __restrict__ U,
           const float* __restrict__ W, const float* __restrict__ bias,
           const float* __restrict__ mask, float* __restrict__ out_seq)
{
    constexpr int BT = 4, JJT = 2;
    constexpr int HP = padDim(H), IP = padDim(I), KP = HP + IP;
    constexpr int Q = KP / 4, HQ = HP / 4;
    constexpr int JT = (H + 7) / 8;
    constexpr int JG = (JT + JJT - 1) / JJT;
    constexpr int JTp = JG * JJT;
    constexpr int H3 = 3 * H;
    static_assert(NTH == 32 * JG, "threads = 32 per jj-group");

    extern __shared__ float smem[];
    float* sW   = smem;                     // JTp*3*KP (rows zero-padded)
    float* sv   = sW + JTp * 3 * KP;        // 2*BT*KP  double-buffered [h|x]
    float* sbz  = sv + 2 * BT * KP;
    float* sbr  = sbz + JTp;
    float* sbrh = sbr + JTp;
    float* sbxh = sbrh + JTp;
    float* smk  = sbxh + JTp;               // 2*BT
    constexpr int SMTOT = JTp * 3 * KP + 2 * BT * KP + 4 * JTp + 2 * BT;

    const int tid  = threadIdx.x;
    const int rank = blockIdx.x & 7;
    const int ci   = blockIdx.x >> 3;
    const int b0   = ci * BT;
    const int j0   = rank * JT;

    for (int e = tid; e < SMTOT; e += NTH) smem[e] = 0.f;
    __syncthreads();

    // weights: row (jj,g) = [U[:,g*H+j] (k<HP) | W[:,g*H+j] (k>=HP)], zero-padded
    for (int e = tid; e < JT * 3 * KP; e += NTH) {
        int jj = e / (3 * KP);
        int r  = e - jj * (3 * KP);
        int g  = r / KP;
        int k  = r - g * KP;
        int j  = j0 + jj;
        float val = 0.f;
        if (j < H) {
            if (k < HP) { if (k < H) val = U[k * H3 + g * H + j]; }
            else { int i = k - HP; if (i < I) val = W[i * H3 + g * H + j]; }
        }
        sW[(jj * 3 + g) * KP + k] = val;
    }
    if (tid < JT) {
        int j = j0 + tid;
        if (j < H) {
            sbz[tid]  = bias[j] + bias[H3 + j];
            sbr[tid]  = bias[H + j] + bias[H3 + H + j];
            sbxh[tid] = bias[2 * H + j];
            sbrh[tid] = bias[H3 + 2 * H + j];
        }
    }
    __syncthreads();

    const uint32_t svu = smem_u32(sv);
    uint32_t rb[8];
#pragma unroll
    for (int r = 0; r < 8; r++) rb[r] = mapa_shared(svu, (uint32_t)r);

    // stage x(0), mask(0) into phase 0
    constexpr int XOPS = BT * (IP / 4);
    for (int e = tid; e < XOPS; e += NTH) {
        int bb = e / (IP / 4), i4 = e - bb * (IP / 4);
        cp_async16(svu + (uint32_t)((bb * KP + HP + i4 * 4) * 4),
                   in_seq + ((size_t)(b0 + bb) * TT) * IP + i4 * 4);
    }
    if (UM && tid < BT)
        cp_async4(smem_u32(smk + tid), mask + (size_t)(b0 + tid) * TT);
    cp_commit();
    cp_wait0();
    cluster_sync_();

    const int w = tid >> 5, lane = tid & 31;
    // owner decode: item = bit-reversal of lane bits 0..2; item = b*2 + jl
    const int oitem = ((lane & 1) << 2) | (lane & 2) | ((lane & 4) >> 2);
    const int ob = oitem >> 1, ojl = oitem & 1;
    const int ojj = w * JJT + ojl;
    const int oj  = j0 + ojj;
    const bool oval = (lane < 8) && (ojj < JT) && (oj < H);

    int p = 0;
    for (int t = 0; t < TT; t++) {
        const int nxt = 1 - p;
        // prefetch x(t+1), mask(t+1) into phase nxt
        if (t + 1 < TT) {
            for (int e = tid; e < XOPS; e += NTH) {
                int bb = e / (IP / 4), i4 = e - bb * (IP / 4);
                cp_async16(svu + (uint32_t)(((nxt * BT + bb) * KP + HP + i4 * 4) * 4),
                           in_seq + ((size_t)(b0 + bb) * TT + (t + 1)) * IP + i4 * 4);
            }
            if (UM && tid < BT)
                cp_async4(smem_u32(smk + nxt * BT + tid),
                          mask + (size_t)(b0 + tid) * TT + (t + 1));
        }
        cp_commit();

        // ---- main accumulation: warp covers 4 b x 2 jj, lanes stride quads
        const float* vc = sv + p * BT * KP;
        float accf[32];
#pragma unroll
        for (int a = 0; a < 32; a++) accf[a] = 0.f;

        for (int g4 = lane; g4 < Q; g4 += 32) {
            const float* vq = vc + g4 * 4;
            float4 vb[BT];
#pragma unroll
            for (int b = 0; b < BT; ++b)
                vb[b] = *reinterpret_cast<const float4*>(vq + b * KP);
            float4 whv[JJT];
#pragma unroll
            for (int jl = 0; jl < JJT; ++jl) {
                const float* wb = sW + ((w * JJT + jl) * 3) * KP + g4 * 4;
                float4 wz = *reinterpret_cast<const float4*>(wb);
                float4 wr = *reinterpret_cast<const float4*>(wb + KP);
                whv[jl]   = *reinterpret_cast<const float4*>(wb + 2 * KP);
#pragma unroll
                for (int b = 0; b < BT; ++b) {
                    const int a = (b * JJT + jl) * 4;
                    accf[a+0] = fmaf(vb[b].x, wz.x, accf[a+0]);
                    accf[a+0] = fmaf(vb[b].y, wz.y, accf[a+0]);
                    accf[a+0] = fmaf(vb[b].z, wz.z, accf[a+0]);
                    accf[a+0] = fmaf(vb[b].w, wz.w, accf[a+0]);
                    accf[a+1] = fmaf(vb[b].x, wr.x, accf[a+1]);
                    accf[a+1] = fmaf(vb[b].y, wr.y, accf[a+1]);
                    accf[a+1] = fmaf(vb[b].z, wr.z, accf[a+1]);
                    accf[a+1] = fmaf(vb[b].w, wr.w, accf[a+1]);
                }
            }
            if (g4 < HQ) {   // h-range: gate-h -> recurrent accumulator (a+2)
#pragma unroll
                for (int jl = 0; jl < JJT; ++jl)
#pragma unroll
                    for (int b = 0; b < BT; ++b) {
                        const int a = (b * JJT + jl) * 4;
                        accf[a+2] = fmaf(vb[b].x, whv[jl].x, accf[a+2]);
                        accf[a+2] = fmaf(vb[b].y, whv[jl].y, accf[a+2]);
                        accf[a+2] = fmaf(vb[b].z, whv[jl].z, accf[a+2]);
                        accf[a+2] = fmaf(vb[b].w, whv[jl].w, accf[a+2]);
                    }
            } else {         // x-range: gate-h -> input accumulator (a+3)
#pragma unroll
                for (int jl = 0; jl < JJT; ++jl)
#pragma unroll
                    for (int b = 0; b < BT; ++b) {
                        const int a = (b * JJT + jl) * 4;
                        accf[a+3] = fmaf(vb[b].x, whv[jl].x, accf[a+3]);
                        accf[a+3] = fmaf(vb[b].y, whv[jl].y, accf[a+3]);
                        accf[a+3] = fmaf(vb[b].z, whv[jl].z, accf[a+3]);
                        accf[a+3] = fmaf(vb[b].w, whv[jl].w, accf[a+3]);
                    }
            }
        }

        // ---- splitting butterfly: 3 rounds over lane bits 0..2 (32 -> 4 accs)
#pragma unroll
        for (int s = 0; s < 3; ++s) {
            const int n = 32 >> (s + 1);
            const bool hi = (lane >> s) & 1;
#pragma unroll
            for (int i = 0; i < n; ++i) {
                float send = hi ? accf[i] : accf[i + n];
                float recv = __shfl_xor_sync(0xffffffffu, send, 1 << s);
                accf[i] = (hi ? accf[i + n] : accf[i]) + recv;
            }
        }
        // broadcast-add across lane bits 3 and 4, keeping all 4 gate accs
#pragma unroll
        for (int m = 8; m <= 16; m <<= 1)
#pragma unroll
            for (int i = 0; i < 4; ++i)
                accf[i] += __shfl_xor_sync(0xffffffffu, accf[i], m);

        // ---- in-register epilogue on owner lanes
        if (oval) {
            float az  = accf[0] + sbz[ojj];
            float ar  = accf[1] + sbr[ojj];
            float arh = accf[2] + sbrh[ojj];
            float axh = accf[3] + sbxh[ojj];
            float z = HSIG ? hsig(az) : sigm(az);
            float r = HSIG ? hsig(ar) : sigm(ar);
            float hh = axh + r * arh;
            if (TANHA) hh = tanhf(hh);
            float hprev = vc[ob * KP + oj];
            float hn = z * hprev + (1.f - z) * hh;
            if (UM) { if (smk[p * BT + ob] == 0.f) hn = hprev; }

            const uint32_t off = (uint32_t)(((nxt * BT + ob) * KP + oj) * 4);
#pragma unroll
            for (int r8 = 0; r8 < 8; r8++) st_cluster_f32(rb[r8] + off, hn);

            if (WSEQ) out_seq[((size_t)(b0 + ob) * TT + t) * HP + oj] = hn;
        }
        cp_wait0();
        cluster_sync_();
        p = nxt;
    }

    if (!WSEQ) {
        if (tid < JT * BT) {
            const int b = tid & 3, jj = tid >> 2;
            const int j = j0 + jj;
            if (j < H) out_seq[(size_t)(b0 + b) * H + j] = sv[(p * BT + b) * KP + j];
        }
    }
}

// ===================== small kernels =====================
__global__ void mask_kernel(const float* __restrict__ x, float* __restrict__ m) {
    int idx = blockIdx.x * blockDim.x + threadIdx.x;
    if (idx < BB * TT) {
        float4 v = ((const float4*)x)[idx];
        m[idx] = (v.x != 0.f || v.y != 0.f || v.z != 0.f || v.w != 0.f) ? 1.f : 0.f;
    }
}

__global__ void combine34_kernel(const float* __restrict__ W3, const float* __restrict__ U3,
                                 const float* __restrict__ b3, const float* __restrict__ W4,
                                 const float* __restrict__ U4, const float* __restrict__ b4,
                                 float* __restrict__ Uc, float* __restrict__ Wc,
                                 float* __restrict__ bc) {
    const int NU = 60 * 180, NW = 150 * 180, NBc = 2 * 180;
    for (int e = blockIdx.x * blockDim.x + threadIdx.x; e < NU + NW + NBc;
         e += gridDim.x * blockDim.x) {
        if (e < NU) {
            int k = e / 180, col = e % 180;
            int g = col / 60, jj = col % 60;
            float v = 0.f;
            if (jj < 30) { if (k < 30)  v = U3[k * 90 + g * 30 + jj]; }
            else         { if (k >= 30) v = U4[(k - 30) * 90 + g * 30 + (jj - 30)]; }
            Uc[e] = v;
        } else if (e < NU + NW) {
            int e2 = e - NU;
            int i = e2 / 180, col = e2 % 180;
            int g = col / 60, jj = col % 60;
            Wc[e2] = (jj < 30) ? W3[i * 90 + g * 30 + jj] : W4[i * 90 + g * 30 + (jj - 30)];
        } else {
            int e2 = e - NU - NW;
            int rr = e2 / 180, col = e2 % 180;
            int g = col / 60, jj = col % 60;
            bc[e2] = (jj < 30) ? b3[rr * 90 + g * 30 + jj] : b4[rr * 90 + g * 30 + (jj - 30)];
        }
    }
}

__global__ void z_kernel(const float* __restrict__ h34, const float* __restrict__ eps,
                         float* __restrict__ z) {
    int idx = blockIdx.x * blockDim.x + threadIdx.x;
    if (idx < BB * 30) {
        int b = idx / 30, c = idx % 30;
        z[idx] = h34[b * 60 + c] + expf(0.5f * h34[b * 60 + 30 + c]) * eps[idx];
    }
}

__global__ void decin_kernel(const float* __restrict__ z, const float* __restrict__ tin2,
                             const float* __restrict__ masks, float* __restrict__ dec_in) {
    const size_t N = (size_t)BB * TT * 36;
    for (size_t idx = (size_t)blockIdx.x * blockDim.x + threadIdx.x; idx < N;
         idx += (size_t)gridDim.x * blockDim.x) {
        size_t b = idx / ((size_t)TT * 36);
        size_t rem = idx % ((size_t)TT * 36);
        size_t t = rem / 36;
        int c = (int)(rem % 36);
        float v = 0.f;
        if (c < 30)      v = z[b * 30 + c] * masks[(b * TT + t) * 32 + c];
        else if (c < 32) v = tin2[(b * TT + t) * 2 + (c - 30)] * masks[(b * TT + t) * 32 + c];
        dec_in[idx] = v;
    }
}

__global__ void dense_kernel(const float* __restrict__ h6, const float* __restrict__ Wd,
                             const float* __restrict__ bd, const float* __restrict__ dec_masks,
                             float* __restrict__ out) {
    int gtid = blockIdx.x * blockDim.x + threadIdx.x;
    int row = gtid >> 5;
    int lane = gtid & 31;
    if (row >= BB * TT) return;
    float s = 0.f;
    const float* hrow = h6 + (size_t)row * 180;
    for (int k = lane; k < 175; k += 32) s = fmaf(hrow[k], Wd[k], s);
#pragma unroll
    for (int off = 16; off; off >>= 1) s += __shfl_down_sync(0xffffffffu, s, off);
    if (lane == 0) out[row] = tanhf(s + bd[0]) * dec_masks[row];
}

// ===================== host-side launch helper =====================
template <int H, int I, int NTH, bool HSIG, bool TANHA, bool UM, bool WSEQ>
static void launch_gru(const float* in_seq, const float* U, const float* W, const float* bias,
                       const float* mask, float* out_seq) {
    constexpr int BT = 4, JJT = 2;
    constexpr int HP = padDim(H), IP = padDim(I), KP = HP + IP;
    constexpr int JT = (H + 7) / 8;
    constexpr int JG = (JT + JJT - 1) / JJT;
    constexpr int JTp = JG * JJT;
    constexpr int SMTOT = JTp * 3 * KP + 2 * BT * KP + 4 * JTp + 2 * BT;
    constexpr int smem_bytes = SMTOT * 4;
    auto fn = gru_kernel<H, I, NTH, HSIG, TANHA, UM, WSEQ>;
    cudaFuncSetAttribute(fn, cudaFuncAttributeMaxDynamicSharedMemorySize, smem_bytes);
    cudaFuncSetAttribute(fn, cudaFuncAttributeNonPortableClusterSizeAllowed, 1);
    fn<<<256, NTH, smem_bytes>>>(in_seq, U, W, bias, mask, out_seq);
}

extern "C" void kernel_launch(void* const* d_in, const int* in_sizes, int n_in,
                              void* d_out, int out_size) {
    const float* x         = (const float*)d_in[0];
    const float* tin2      = (const float*)d_in[1];
    const float* masks     = (const float*)d_in[2];
    const float* dec_masks = (const float*)d_in[3];
    const float* eps       = (const float*)d_in[4];
    const float* W1 = (const float*)d_in[5];
    const float* U1 = (const float*)d_in[6];
    const float* b1 = (const float*)d_in[7];
    const float* W2 = (const float*)d_in[8];
    const float* U2 = (const float*)d_in[9];
    const float* b2 = (const float*)d_in[10];
    const float* W3 = (const float*)d_in[11];
    const float* U3 = (const float*)d_in[12];
    const float* b3 = (const float*)d_in[13];
    const float* W4 = (const float*)d_in[14];
    const float* U4 = (const float*)d_in[15];
    const float* b4 = (const float*)d_in[16];
    const float* W5 = (const float*)d_in[17];
    const float* U5 = (const float*)d_in[18];
    const float* b5 = (const float*)d_in[19];
    const float* W6 = (const float*)d_in[20];
    const float* U6 = (const float*)d_in[21];
    const float* b6 = (const float*)d_in[22];
    const float* Wd = (const float*)d_in[23];
    const float* bd = (const float*)d_in[24];
    float* out = (float*)d_out;

    void *pA, *pB, *pM, *pH34, *pZ, *pUc, *pWc, *pBc;
    cudaGetSymbolAddress(&pA, g_bufA);
    cudaGetSymbolAddress(&pB, g_bufB);
    cudaGetSymbolAddress(&pM, g_mask);
    cudaGetSymbolAddress(&pH34, g_h34);
    cudaGetSymbolAddress(&pZ, g_z);
    cudaGetSymbolAddress(&pUc, g_Uc);
    cudaGetSymbolAddress(&pWc, g_Wc);
    cudaGetSymbolAddress(&pBc, g_bc);
    float* bufA = (float*)pA;
    float* bufB = (float*)pB;
    float* mptr = (float*)pM;
    float* h34  = (float*)pH34;
    float* zbuf = (float*)pZ;
    float* Uc   = (float*)pUc;
    float* Wc   = (float*)pWc;
    float* Bc   = (float*)pBc;

    mask_kernel<<<(BB * TT + 255) / 256, 256>>>(x, mptr);
    combine34_kernel<<<64, 256>>>(W3, U3, b3, W4, U4, b4, Uc, Wc, Bc);

    // encoder GRU1 (H=175, I=4): JT=22 -> JG=11 -> 352 threads
    launch_gru<175, 4, 352, true, true, true, true>(x, U1, W1, b1, mptr, bufA);
    // encoder GRU2 (H=150, I=175): JT=19 -> JG=10 -> 320 threads
    launch_gru<150, 175, 320, true, true, true, true>(bufA, U2, W2, b2, mptr, bufB);
    // fused GRU3+GRU4 (H=60, I=150): JT=8 -> JG=4 -> 128 threads, final state only
    launch_gru<60, 150, 128, false, false, true, false>(bufB, Uc, Wc, Bc, mptr, h34);

    z_kernel<<<(BB * 30 + 255) / 256, 256>>>(h34, eps, zbuf);
    decin_kernel<<<2048, 256>>>(zbuf, tin2, masks, bufA);

    // decoder GRU5 (H=150, I=32): 320 threads
    launch_gru<150, 32, 320, true, true, false, true>(bufA, U5, W5, b5, nullptr, bufB);
    // decoder GRU6 (H=175, I=150): 352 threads
    launch_gru<175, 150, 352, true, true, false, true>(bufB, U6, W6, b6, nullptr, bufA);

    dense_kernel<<<(BB * TT + 7) / 8, 256>>>(bufA, Wd, bd, dec_masks, out);
}